// round 2
// baseline (speedup 1.0000x reference)
#include <cuda_runtime.h>
#include <math.h>
#include <stdint.h>

#define T_ENDF   100.0f
#define NTAB     8192
#define NBATCH   16
#define MAXLEN   384
#define NHID     128
#define NMC      15
#define EPSV     1e-10f
#define U_TOTAL  92160u   /* 15*16*384 */
#define U_HALF   46080u

// ---------------- device scratch (no allocations allowed) ----------------
__device__ float  g_table[NTAB];
__device__ double g_sum_log;
__device__ double g_lamb_ints;

// ---------------- small helpers ----------------
__device__ __forceinline__ float softplusf(float x) {
    return fmaxf(x, 0.f) + log1pf(expf(-fabsf(x)));
}

__device__ __forceinline__ uint32_t rotl32(uint32_t x, int r) {
    return (x << r) | (x >> (32 - r));
}

// Reproduce jax.random.uniform(jax.random.key(42), (15,16,384)) element idx.
// key(42) -> (k0,k1) = (0, 42). counts = iota(92160); split in halves:
//   idx <  46080 : out0 of threefry2x32(k, (idx, idx+46080))
//   idx >= 46080 : out1 of threefry2x32(k, (idx-46080, idx))
// float: bitcast(0x3f800000 | bits>>9) - 1
__device__ __forceinline__ float jax_uniform(uint32_t idx) {
    const uint32_t k0 = 0u, k1 = 42u;
    const uint32_t k2 = 0x1BD11BDAu ^ k0 ^ k1;
    bool lo = idx < U_HALF;
    uint32_t x0 = lo ? idx : idx - U_HALF;
    uint32_t x1 = lo ? idx + U_HALF : idx;
    x0 += k0; x1 += k1;
#define TF_RND(r) { x0 += x1; x1 = rotl32(x1, r); x1 ^= x0; }
    TF_RND(13) TF_RND(15) TF_RND(26) TF_RND(6);  x0 += k1; x1 += k2 + 1u;
    TF_RND(17) TF_RND(29) TF_RND(16) TF_RND(24); x0 += k2; x1 += k0 + 2u;
    TF_RND(13) TF_RND(15) TF_RND(26) TF_RND(6);  x0 += k0; x1 += k1 + 3u;
    TF_RND(17) TF_RND(29) TF_RND(16) TF_RND(24); x0 += k1; x1 += k2 + 4u;
    TF_RND(13) TF_RND(15) TF_RND(26) TF_RND(6);  x0 += k2; x1 += k0 + 5u;
#undef TF_RND
    uint32_t bits = lo ? x0 : x1;
    return __uint_as_float(0x3f800000u | (bits >> 9)) - 1.0f;
}

// Catmull-Rom lookup of f(x), x in [0, 100]. Error O(h^4) ~ 1e-9 abs.
__device__ __forceinline__ float table_f(float x) {
    const float scale = (float)(NTAB - 1) / T_ENDF;
    float p = x * scale;
    int k = __float2int_rd(p);
    k = max(1, min(k, NTAB - 3));
    float fr = p - (float)k;
    float p0 = g_table[k - 1];
    float p1 = g_table[k];
    float p2 = g_table[k + 1];
    float p3 = g_table[k + 2];
    float m1 = 0.5f * (p2 - p0);
    float m2 = 0.5f * (p3 - p1);
    float d  = p2 - p1;
    return p1 + fr * (m1 + fr * ((3.f * d - 2.f * m1 - m2) + fr * (m1 + m2 - 2.f * d)));
}

// ---------------- kernel 0: zero accumulators ----------------
__global__ void init_kernel() {
    g_sum_log  = 0.0;
    g_lamb_ints = 0.0;
}

// ---------------- kernel 1: build f table ----------------
// 256 blocks x 256 threads; each block computes 32 consecutive grid points.
// Register-tiled fp32 GEMM per hidden layer (32x128 @ 128x128).
__device__ __forceinline__ void layer_gemm(const float* __restrict__ Ash,
                                           float* __restrict__ Csh,
                                           const float* __restrict__ W,
                                           const float* __restrict__ bias,
                                           int tid) {
    int tx = tid & 15, ty = tid >> 4;
    int r0 = ty * 2, c0 = tx * 8;
    float acc0[8], acc1[8];
    float4 bb0 = __ldg((const float4*)(bias + c0));
    float4 bb1 = __ldg((const float4*)(bias + c0 + 4));
    acc0[0] = bb0.x; acc0[1] = bb0.y; acc0[2] = bb0.z; acc0[3] = bb0.w;
    acc0[4] = bb1.x; acc0[5] = bb1.y; acc0[6] = bb1.z; acc0[7] = bb1.w;
#pragma unroll
    for (int q = 0; q < 8; q++) acc1[q] = acc0[q];
#pragma unroll 4
    for (int k = 0; k < 128; k++) {
        float a0 = Ash[r0 * 132 + k];
        float a1 = Ash[r0 * 132 + 132 + k];
        float4 w0 = __ldg((const float4*)(W + k * 128 + c0));
        float4 w1 = __ldg((const float4*)(W + k * 128 + c0 + 4));
        float w[8] = {w0.x, w0.y, w0.z, w0.w, w1.x, w1.y, w1.z, w1.w};
#pragma unroll
        for (int q = 0; q < 8; q++) {
            acc0[q] = fmaf(a0, w[q], acc0[q]);
            acc1[q] = fmaf(a1, w[q], acc1[q]);
        }
    }
#pragma unroll
    for (int q = 0; q < 8; q++) {
        Csh[r0 * 132 + c0 + q]       = tanhf(acc0[q]);
        Csh[(r0 + 1) * 132 + c0 + q] = tanhf(acc1[q]);
    }
}

__global__ __launch_bounds__(256) void build_table_kernel(
    const float* __restrict__ W1, const float* __restrict__ b1,
    const float* __restrict__ W2, const float* __restrict__ b2,
    const float* __restrict__ W3, const float* __restrict__ b3,
    const float* __restrict__ W4, const float* __restrict__ b4) {
    __shared__ float A[32 * 132];
    __shared__ float C[32 * 132];
    const int tid = threadIdx.x;
    const int blk = blockIdx.x;
    const float h = T_ENDF / (float)(NTAB - 1);

    // layer 1: A[v][j] = tanh(x_v * W1[j] + b1[j])
    for (int e = tid; e < 32 * 128; e += 256) {
        int v = e >> 7, j = e & 127;
        float x = (float)(blk * 32 + v) * h;
        A[v * 132 + j] = tanhf(fmaf(x, __ldg(W1 + j), __ldg(b1 + j)));
    }
    __syncthreads();
    layer_gemm(A, C, W2, b2, tid);   // layer 2
    __syncthreads();
    layer_gemm(C, A, W3, b3, tid);   // layer 3
    __syncthreads();
    // head: softplus(A[v] . W4 + b4)
    if (tid < 32) {
        float acc = __ldg(b4);
#pragma unroll 8
        for (int j = 0; j < 128; j++)
            acc = fmaf(A[tid * 132 + j], __ldg(W4 + j), acc);
        g_table[blk * 32 + tid] = softplusf(acc);
    }
}

// ---------------- kernel 2: pair sums + log accumulation ----------------
// one warp per (b, i); 8 warps/block; 768 blocks exactly cover 16*384 warps.
__global__ __launch_bounds__(256) void pairs_kernel(
    const float* __restrict__ t, const int* __restrict__ lens,
    const float* __restrict__ bg) {
    __shared__ double wsum[8];
    int wid_in_blk = threadIdx.x >> 5;
    int lane = threadIdx.x & 31;
    int wg = blockIdx.x * 8 + wid_in_blk;
    int b = wg / MAXLEN;
    int i = wg % MAXLEN;
    float background = __ldg(bg);
    double contrib = 0.0;
    int len = __ldg(lens + b);
    if (i == 0) {
        if (lane == 0) contrib = log((double)background);
    } else if (i < len) {
        const float* tb = t + b * MAXLEN;
        float ti = __ldg(tb + i);
        float s = 0.f;
        for (int j = lane; j < i; j += 32)
            s += table_f(ti - __ldg(tb + j));
#pragma unroll
        for (int o = 16; o; o >>= 1) s += __shfl_down_sync(0xffffffffu, s, o);
        if (lane == 0) contrib = log((double)(s + background));
    }
    if (lane == 0) wsum[wid_in_blk] = contrib;
    __syncthreads();
    if (threadIdx.x == 0) {
        double tot = 0.0;
#pragma unroll
        for (int w = 0; w < 8; w++) tot += wsum[w];
        atomicAdd(&g_sum_log, tot);
    }
}

// ---------------- kernel 3: Monte-Carlo integral ----------------
// one thread per (b, l): 24 blocks x 256 = 6144 threads exactly.
__global__ __launch_bounds__(256) void mc_kernel(
    const float* __restrict__ t, const int* __restrict__ lens) {
    __shared__ double wsum[8];
    int idx = blockIdx.x * 256 + threadIdx.x;  // b*384 + l
    int b = idx / MAXLEN;
    int l = idx % MAXLEN;
    double contrib = 0.0;
    if (l < __ldg(lens + b)) {
        float diff = T_ENDF - __ldg(t + idx);
        float acc = 0.f;
#pragma unroll
        for (int s = 0; s < NMC; s++) {
            float u = jax_uniform((uint32_t)(s * (NBATCH * MAXLEN) + idx));
            acc += table_f(u * diff) + EPSV;
        }
        contrib = (double)(acc * (1.0f / (float)NMC) * diff);
    }
    // warp + block reduce
#pragma unroll
    for (int o = 16; o; o >>= 1) contrib += __shfl_down_sync(0xffffffffu, contrib, o);
    if ((threadIdx.x & 31) == 0) wsum[threadIdx.x >> 5] = contrib;
    __syncthreads();
    if (threadIdx.x == 0) {
        double tot = 0.0;
#pragma unroll
        for (int w = 0; w < 8; w++) tot += wsum[w];
        atomicAdd(&g_lamb_ints, tot);
    }
}

// ---------------- kernel 4: finalize ----------------
__global__ void finalize_kernel(const float* __restrict__ bg, float* __restrict__ out) {
    double ints = g_lamb_ints + (double)NBATCH * 100.0 * (double)__ldg(bg);
    out[0] = (float)(-(g_sum_log - ints) / (double)NBATCH);
}

// ---------------- launch ----------------
extern "C" void kernel_launch(void* const* d_in, const int* in_sizes, int n_in,
                              void* d_out, int out_size) {
    const float* seq_pads  = (const float*)d_in[0];   // [16,384,1]
    const int*   seq_lens  = (const int*)  d_in[1];   // [16]
    const float* background= (const float*)d_in[2];   // [1]
    const float* W1 = (const float*)d_in[3];
    const float* b1 = (const float*)d_in[4];
    const float* W2 = (const float*)d_in[5];
    const float* b2 = (const float*)d_in[6];
    const float* W3 = (const float*)d_in[7];
    const float* b3 = (const float*)d_in[8];
    const float* W4 = (const float*)d_in[9];
    const float* b4 = (const float*)d_in[10];
    float* out = (float*)d_out;

    init_kernel<<<1, 1>>>();
    build_table_kernel<<<NTAB / 32, 256>>>(W1, b1, W2, b2, W3, b3, W4, b4);
    pairs_kernel<<<(NBATCH * MAXLEN) / 8, 256>>>(seq_pads, seq_lens, background);
    mc_kernel<<<(NBATCH * MAXLEN) / 256, 256>>>(seq_pads, seq_lens);
    finalize_kernel<<<1, 1>>>(background, out);
}

// round 6
// speedup vs baseline: 1.1044x; 1.1044x over previous
#include <cuda_runtime.h>
#include <math.h>
#include <stdint.h>

#define T_ENDF   100.0f
#define NTAB     4096
#define NBATCH   16
#define MAXLEN   384
#define NHID     128
#define NMC      15
#define EPSV     1e-10f
#define U_TOTAL  92160u   /* 15*16*384 */
#define U_HALF   46080u
#define PAIR_BLOCKS  768  /* 16*384 warps / 8 warps per block */
#define MC_BLOCKS    360  /* 92160 / 256 */

// ---------------- device scratch (no allocations allowed) ----------------
__device__ float  g_table[NTAB];
__device__ float4 g_coef[NTAB];
__device__ double g_sum_log;
__device__ double g_lamb_ints;

// ---------------- small helpers ----------------
__device__ __forceinline__ float softplusf(float x) {
    return fmaxf(x, 0.f) + log1pf(expf(-fabsf(x)));
}

__device__ __forceinline__ uint32_t rotl32(uint32_t x, int r) {
    return (x << r) | (x >> (32 - r));
}

// Reproduce jax.random.uniform(jax.random.key(42), (15,16,384)) element idx.
// key(42) -> (k0,k1) = (0, 42). counts = iota(92160); split in halves:
//   idx <  46080 : out0 of threefry2x32(k, (idx, idx+46080))
//   idx >= 46080 : out1 of threefry2x32(k, (idx-46080, idx))
__device__ __forceinline__ float jax_uniform(uint32_t idx) {
    const uint32_t k0 = 0u, k1 = 42u;
    const uint32_t k2 = 0x1BD11BDAu ^ k0 ^ k1;
    bool lo = idx < U_HALF;
    uint32_t x0 = lo ? idx : idx - U_HALF;
    uint32_t x1 = lo ? idx + U_HALF : idx;
    x0 += k0; x1 += k1;
#define TF_RND(r) { x0 += x1; x1 = rotl32(x1, r); x1 ^= x0; }
    TF_RND(13) TF_RND(15) TF_RND(26) TF_RND(6);  x0 += k1; x1 += k2 + 1u;
    TF_RND(17) TF_RND(29) TF_RND(16) TF_RND(24); x0 += k2; x1 += k0 + 2u;
    TF_RND(13) TF_RND(15) TF_RND(26) TF_RND(6);  x0 += k0; x1 += k1 + 3u;
    TF_RND(17) TF_RND(29) TF_RND(16) TF_RND(24); x0 += k1; x1 += k2 + 4u;
    TF_RND(13) TF_RND(15) TF_RND(26) TF_RND(6);  x0 += k2; x1 += k0 + 5u;
#undef TF_RND
    uint32_t bits = lo ? x0 : x1;
    return __uint_as_float(0x3f800000u | (bits >> 9)) - 1.0f;
}

// Cubic (Catmull-Rom coefficient) lookup of f(x), x in [0, 100].
// One LDG.128 + 3 FMA.
__device__ __forceinline__ float table_f(float x) {
    const float scale = (float)(NTAB - 1) / T_ENDF;
    float p = x * scale;
    int k = __float2int_rd(p);
    k = max(0, min(k, NTAB - 2));
    float fr = p - (float)k;
    float4 c = g_coef[k];
    return fmaf(fmaf(fmaf(c.w, fr, c.z), fr, c.y), fr, c.x);
}

// ---------------- kernel 1: build f table (values) ----------------
// 128 blocks x 256 threads; each block computes 32 consecutive grid points.
// Register-tiled fp32 GEMM per hidden layer (32x128 @ 128x128).
__device__ __forceinline__ void layer_gemm(const float* __restrict__ Ash,
                                           float* __restrict__ Csh,
                                           const float* __restrict__ W,
                                           const float* __restrict__ bias,
                                           int tid) {
    int tx = tid & 15, ty = tid >> 4;
    int r0 = ty * 2, c0 = tx * 8;
    float acc0[8], acc1[8];
    float4 bb0 = __ldg((const float4*)(bias + c0));
    float4 bb1 = __ldg((const float4*)(bias + c0 + 4));
    acc0[0] = bb0.x; acc0[1] = bb0.y; acc0[2] = bb0.z; acc0[3] = bb0.w;
    acc0[4] = bb1.x; acc0[5] = bb1.y; acc0[6] = bb1.z; acc0[7] = bb1.w;
#pragma unroll
    for (int q = 0; q < 8; q++) acc1[q] = acc0[q];
#pragma unroll 4
    for (int k = 0; k < 128; k++) {
        float a0 = Ash[r0 * 132 + k];
        float a1 = Ash[r0 * 132 + 132 + k];
        float4 w0 = __ldg((const float4*)(W + k * 128 + c0));
        float4 w1 = __ldg((const float4*)(W + k * 128 + c0 + 4));
        float w[8] = {w0.x, w0.y, w0.z, w0.w, w1.x, w1.y, w1.z, w1.w};
#pragma unroll
        for (int q = 0; q < 8; q++) {
            acc0[q] = fmaf(a0, w[q], acc0[q]);
            acc1[q] = fmaf(a1, w[q], acc1[q]);
        }
    }
#pragma unroll
    for (int q = 0; q < 8; q++) {
        Csh[r0 * 132 + c0 + q]       = tanhf(acc0[q]);
        Csh[(r0 + 1) * 132 + c0 + q] = tanhf(acc1[q]);
    }
}

__global__ __launch_bounds__(256) void build_table_kernel(
    const float* __restrict__ W1, const float* __restrict__ b1,
    const float* __restrict__ W2, const float* __restrict__ b2,
    const float* __restrict__ W3, const float* __restrict__ b3,
    const float* __restrict__ W4, const float* __restrict__ b4) {
    __shared__ float A[32 * 132];
    __shared__ float C[32 * 132];
    const int tid = threadIdx.x;
    const int blk = blockIdx.x;
    if (blk == 0 && tid == 0) { g_sum_log = 0.0; g_lamb_ints = 0.0; }
    const float h = T_ENDF / (float)(NTAB - 1);

    // layer 1: A[v][j] = tanh(x_v * W1[j] + b1[j])
    for (int e = tid; e < 32 * 128; e += 256) {
        int v = e >> 7, j = e & 127;
        float x = (float)(blk * 32 + v) * h;
        A[v * 132 + j] = tanhf(fmaf(x, __ldg(W1 + j), __ldg(b1 + j)));
    }
    __syncthreads();
    layer_gemm(A, C, W2, b2, tid);   // layer 2
    __syncthreads();
    layer_gemm(C, A, W3, b3, tid);   // layer 3
    __syncthreads();
    // head: softplus(A[v] . W4 + b4)
    if (tid < 32) {
        float acc = __ldg(b4);
#pragma unroll 8
        for (int j = 0; j < 128; j++)
            acc = fmaf(A[tid * 132 + j], __ldg(W4 + j), acc);
        g_table[blk * 32 + tid] = softplusf(acc);
    }
}

// ---------------- kernel 2: build per-interval cubic coefficients ----------
__global__ __launch_bounds__(256) void coef_kernel() {
    int k = blockIdx.x * 256 + threadIdx.x;
    if (k >= NTAB - 1) return;
    float p1 = g_table[k], p2 = g_table[k + 1];
    float m1, m2;
    if (k == 0)
        m1 = fmaf(-1.5f, g_table[0], fmaf(2.0f, g_table[1], -0.5f * g_table[2]));
    else
        m1 = 0.5f * (g_table[k + 1] - g_table[k - 1]);
    if (k == NTAB - 2)
        m2 = fmaf(1.5f, g_table[NTAB - 1], fmaf(-2.0f, g_table[NTAB - 2], 0.5f * g_table[NTAB - 3]));
    else
        m2 = 0.5f * (g_table[k + 2] - g_table[k]);
    float d = p2 - p1;
    g_coef[k] = make_float4(p1, m1, 3.f * d - 2.f * m1 - m2, m1 + m2 - 2.f * d);
}

// ---------------- kernel 3: fused pairs + Monte-Carlo ----------------
// blocks [0, PAIR_BLOCKS): one warp per (b, i), 8 warps/block
// blocks [PAIR_BLOCKS, PAIR_BLOCKS+MC_BLOCKS): one thread per (s, b, l)
__global__ __launch_bounds__(256) void fused_kernel(
    const float* __restrict__ t, const int* __restrict__ lens,
    const float* __restrict__ bg) {
    __shared__ double wsum[8];
    const int tid = threadIdx.x;
    if (blockIdx.x < PAIR_BLOCKS) {
        int wid_in_blk = tid >> 5;
        int lane = tid & 31;
        int wg = blockIdx.x * 8 + wid_in_blk;
        int b = wg / MAXLEN;
        int i = wg % MAXLEN;
        float background = __ldg(bg);
        double contrib = 0.0;
        int len = __ldg(lens + b);
        if (i == 0) {
            if (lane == 0) contrib = log((double)background);
        } else if (i < len) {
            const float* tb = t + b * MAXLEN;
            float ti = __ldg(tb + i);
            float s = 0.f;
            for (int j = lane; j < i; j += 32)
                s += table_f(ti - __ldg(tb + j));
#pragma unroll
            for (int o = 16; o; o >>= 1) s += __shfl_down_sync(0xffffffffu, s, o);
            if (lane == 0) contrib = log((double)(s + background));
        }
        if (lane == 0) wsum[wid_in_blk] = contrib;
        __syncthreads();
        if (tid == 0) {
            double tot = 0.0;
#pragma unroll
            for (int w = 0; w < 8; w++) tot += wsum[w];
            atomicAdd(&g_sum_log, tot);
        }
    } else {
        // MC: linear index e over [0, 92160); e = s*6144 + b*384 + l
        uint32_t e = (blockIdx.x - PAIR_BLOCKS) * 256u + (uint32_t)tid;
        uint32_t r = e % (NBATCH * MAXLEN);     // b*384 + l
        int b = r / MAXLEN;
        int l = r % MAXLEN;
        double contrib = 0.0;
        if (l < __ldg(lens + b)) {
            float diff = T_ENDF - __ldg(t + r);
            float u = jax_uniform(e);
            contrib = (double)((table_f(u * diff) + EPSV) * diff * (1.0f / (float)NMC));
        }
#pragma unroll
        for (int o = 16; o; o >>= 1) contrib += __shfl_down_sync(0xffffffffu, contrib, o);
        if ((tid & 31) == 0) wsum[tid >> 5] = contrib;
        __syncthreads();
        if (tid == 0) {
            double tot = 0.0;
#pragma unroll
            for (int w = 0; w < 8; w++) tot += wsum[w];
            atomicAdd(&g_lamb_ints, tot);
        }
    }
}

// ---------------- kernel 4: finalize ----------------
__global__ void finalize_kernel(const float* __restrict__ bg, float* __restrict__ out) {
    double ints = g_lamb_ints + (double)NBATCH * 100.0 * (double)__ldg(bg);
    out[0] = (float)(-(g_sum_log - ints) / (double)NBATCH);
}

// ---------------- launch ----------------
extern "C" void kernel_launch(void* const* d_in, const int* in_sizes, int n_in,
                              void* d_out, int out_size) {
    const float* seq_pads  = (const float*)d_in[0];   // [16,384,1]
    const int*   seq_lens  = (const int*)  d_in[1];   // [16]
    const float* background= (const float*)d_in[2];   // [1]
    const float* W1 = (const float*)d_in[3];
    const float* b1 = (const float*)d_in[4];
    const float* W2 = (const float*)d_in[5];
    const float* b2 = (const float*)d_in[6];
    const float* W3 = (const float*)d_in[7];
    const float* b3 = (const float*)d_in[8];
    const float* W4 = (const float*)d_in[9];
    const float* b4 = (const float*)d_in[10];
    float* out = (float*)d_out;

    build_table_kernel<<<NTAB / 32, 256>>>(W1, b1, W2, b2, W3, b3, W4, b4);
    coef_kernel<<<(NTAB + 255) / 256, 256>>>();
    fused_kernel<<<PAIR_BLOCKS + MC_BLOCKS, 256>>>(seq_pads, seq_lens, background);
    finalize_kernel<<<1, 1>>>(background, out);
}

// round 7
// speedup vs baseline: 2.1086x; 1.9093x over previous
#include <cuda_runtime.h>
#include <math.h>
#include <stdint.h>

#define T_ENDF   100.0f
#define NTAB     2048
#define NBATCH   16
#define MAXLEN   384
#define NMC      15
#define EPSV     1e-10f
#define U_HALF   46080u
#define PAIR_BLOCKS  768  /* 16*384 warps / 8 warps per block */
#define MC_BLOCKS    360  /* 92160 / 256 */
#define TOTAL_BLOCKS (PAIR_BLOCKS + MC_BLOCKS)

// ---------------- device scratch (no allocations allowed) ----------------
__device__ float4 g_coef[NTAB];
__device__ double g_sum_log;
__device__ double g_lamb_ints;
__device__ unsigned g_done;

// ---------------- small helpers ----------------
__device__ __forceinline__ float softplusf(float x) {
    return fmaxf(x, 0.f) + log1pf(expf(-fabsf(x)));
}

__device__ __forceinline__ uint32_t rotl32(uint32_t x, int r) {
    return (x << r) | (x >> (32 - r));
}

// Reproduce jax.random.uniform(jax.random.key(42), (15,16,384)) element idx.
__device__ __forceinline__ float jax_uniform(uint32_t idx) {
    const uint32_t k0 = 0u, k1 = 42u;
    const uint32_t k2 = 0x1BD11BDAu ^ k0 ^ k1;
    bool lo = idx < U_HALF;
    uint32_t x0 = lo ? idx : idx - U_HALF;
    uint32_t x1 = lo ? idx + U_HALF : idx;
    x0 += k0; x1 += k1;
#define TF_RND(r) { x0 += x1; x1 = rotl32(x1, r); x1 ^= x0; }
    TF_RND(13) TF_RND(15) TF_RND(26) TF_RND(6);  x0 += k1; x1 += k2 + 1u;
    TF_RND(17) TF_RND(29) TF_RND(16) TF_RND(24); x0 += k2; x1 += k0 + 2u;
    TF_RND(13) TF_RND(15) TF_RND(26) TF_RND(6);  x0 += k0; x1 += k1 + 3u;
    TF_RND(17) TF_RND(29) TF_RND(16) TF_RND(24); x0 += k1; x1 += k2 + 4u;
    TF_RND(13) TF_RND(15) TF_RND(26) TF_RND(6);  x0 += k2; x1 += k0 + 5u;
#undef TF_RND
    uint32_t bits = lo ? x0 : x1;
    return __uint_as_float(0x3f800000u | (bits >> 9)) - 1.0f;
}

// Cubic lookup of f(x), x in [0, 100]: one LDG.128 + 3 FMA.
__device__ __forceinline__ float table_f(float x) {
    const float scale = (float)(NTAB - 1) / T_ENDF;
    float p = x * scale;
    int k = __float2int_rd(p);
    k = max(0, min(k, NTAB - 2));
    float fr = p - (float)k;
    float4 c = g_coef[k];
    return fmaf(fmaf(fmaf(c.w, fr, c.z), fr, c.y), fr, c.x);
}

// ---------------- kernel 1: fused table build + cubic coefficients --------
// 128 blocks x 256 threads. Block handles 16 intervals [blk*16, blk*16+16);
// computes MLP at 20 grid points (1-left / 3-right halo incl. padding) and
// writes Catmull-Rom coefficients directly. No separate coef pass.
#define BROWS 20
#define ASTRIDE 132   /* multiple of 4 for LDS.128; broadcast reads: no conflicts */

__device__ __forceinline__ void layer20(const float* __restrict__ Ash,
                                        float* __restrict__ Csh,
                                        const float* __restrict__ W,
                                        const float* __restrict__ bias,
                                        int tid) {
    int grp = tid >> 7;          // 0: rows 0-9, 1: rows 10-19
    int c = tid & 127;
    int r0 = grp * 10;
    float acc[10];
    float bv = __ldg(bias + c);
#pragma unroll
    for (int q = 0; q < 10; q++) acc[q] = bv;
    for (int k4 = 0; k4 < 32; k4++) {
        float w0 = __ldg(W + (k4 * 4 + 0) * 128 + c);
        float w1 = __ldg(W + (k4 * 4 + 1) * 128 + c);
        float w2 = __ldg(W + (k4 * 4 + 2) * 128 + c);
        float w3 = __ldg(W + (k4 * 4 + 3) * 128 + c);
#pragma unroll
        for (int q = 0; q < 10; q++) {
            float4 a = *(const float4*)(Ash + (r0 + q) * ASTRIDE + k4 * 4);
            acc[q] = fmaf(a.x, w0, acc[q]);
            acc[q] = fmaf(a.y, w1, acc[q]);
            acc[q] = fmaf(a.z, w2, acc[q]);
            acc[q] = fmaf(a.w, w3, acc[q]);
        }
    }
#pragma unroll
    for (int q = 0; q < 10; q++)
        Csh[(r0 + q) * ASTRIDE + c] = tanhf(acc[q]);
}

__global__ __launch_bounds__(256) void build_coef_kernel(
    const float* __restrict__ W1, const float* __restrict__ b1,
    const float* __restrict__ W2, const float* __restrict__ b2,
    const float* __restrict__ W3, const float* __restrict__ b3,
    const float* __restrict__ W4, const float* __restrict__ b4) {
    __shared__ float A[BROWS * ASTRIDE];
    __shared__ float C[BROWS * ASTRIDE];
    __shared__ float val[BROWS];
    const int tid = threadIdx.x;
    const int blk = blockIdx.x;
    if (blk == 0 && tid == 0) { g_sum_log = 0.0; g_lamb_ints = 0.0; g_done = 0u; }
    const float h = T_ENDF / (float)(NTAB - 1);
    const int base = blk * 16 - 1;          // grid-point index of local row 0

    // layer 1: A[j][c] = tanh(x_j * W1[c] + b1[c]), 20 rows (clamped points)
    for (int e = tid; e < BROWS * 128; e += 256) {
        int j = e >> 7, c = e & 127;
        int p = base + j;
        p = max(0, min(p, NTAB - 1));
        float x = (float)p * h;
        A[j * ASTRIDE + c] = tanhf(fmaf(x, __ldg(W1 + c), __ldg(b1 + c)));
    }
    __syncthreads();
    layer20(A, C, W2, b2, tid);   // layer 2
    __syncthreads();
    layer20(C, A, W3, b3, tid);   // layer 3
    __syncthreads();
    // head: val[j] = softplus(A[j] . W4 + b4); 8 threads per row
    if (tid < BROWS * 8) {
        int j = tid >> 3, l8 = tid & 7;
        float acc = 0.f;
#pragma unroll
        for (int q = 0; q < 16; q++) {
            int cc = l8 + (q << 3);
            acc = fmaf(A[j * ASTRIDE + cc], __ldg(W4 + cc), acc);
        }
        acc += __shfl_down_sync(0xffffffffu, acc, 4, 8);
        acc += __shfl_down_sync(0xffffffffu, acc, 2, 8);
        acc += __shfl_down_sync(0xffffffffu, acc, 1, 8);
        if (l8 == 0) val[j] = softplusf(acc + __ldg(b4));
    }
    __syncthreads();
    // Catmull-Rom coefficients for intervals k = blk*16 + t, t in [0,16)
    if (tid < 16) {
        int k = blk * 16 + tid;
        if (k <= NTAB - 2) {
            float p0 = val[tid], p1 = val[tid + 1], p2 = val[tid + 2], p3 = val[tid + 3];
            float m1 = (k == 0)
                ? fmaf(-1.5f, p1, fmaf(2.0f, p2, -0.5f * p3))
                : 0.5f * (p2 - p0);
            float m2 = (k == NTAB - 2)
                ? fmaf(1.5f, p2, fmaf(-2.0f, p1, 0.5f * p0))
                : 0.5f * (p3 - p1);
            float d = p2 - p1;
            g_coef[k] = make_float4(p1, m1, 3.f * d - 2.f * m1 - m2, m1 + m2 - 2.f * d);
        }
    }
}

// ---------------- kernel 2: fused pairs + Monte-Carlo + finalize ----------
// blocks [0, PAIR_BLOCKS): one warp per (b, i), 8 warps/block
// blocks [PAIR_BLOCKS, TOTAL_BLOCKS): one thread per (s, b, l)
// Last block to finish writes the output (counter reset by build kernel).
__global__ __launch_bounds__(256) void fused_kernel(
    const float* __restrict__ t, const int* __restrict__ lens,
    const float* __restrict__ bg, float* __restrict__ out) {
    __shared__ double wsum[8];
    const int tid = threadIdx.x;
    if (blockIdx.x < PAIR_BLOCKS) {
        int wid_in_blk = tid >> 5;
        int lane = tid & 31;
        int wg = blockIdx.x * 8 + wid_in_blk;
        int b = wg / MAXLEN;
        int i = wg % MAXLEN;
        float background = __ldg(bg);
        double contrib = 0.0;
        int len = __ldg(lens + b);
        if (i == 0) {
            if (lane == 0) contrib = log((double)background);
        } else if (i < len) {
            const float* tb = t + b * MAXLEN;
            float ti = __ldg(tb + i);
            float s = 0.f;
            for (int j = lane; j < i; j += 32)
                s += table_f(ti - __ldg(tb + j));
#pragma unroll
            for (int o = 16; o; o >>= 1) s += __shfl_down_sync(0xffffffffu, s, o);
            if (lane == 0) contrib = log((double)(s + background));
        }
        if (lane == 0) wsum[wid_in_blk] = contrib;
        __syncthreads();
        if (tid == 0) {
            double tot = 0.0;
#pragma unroll
            for (int w = 0; w < 8; w++) tot += wsum[w];
            atomicAdd(&g_sum_log, tot);
        }
    } else {
        // MC: linear index e over [0, 92160); e = s*6144 + b*384 + l
        uint32_t e = (blockIdx.x - PAIR_BLOCKS) * 256u + (uint32_t)tid;
        uint32_t r = e % (NBATCH * MAXLEN);     // b*384 + l
        int b = r / MAXLEN;
        int l = r % MAXLEN;
        double contrib = 0.0;
        if (l < __ldg(lens + b)) {
            float diff = T_ENDF - __ldg(t + r);
            float u = jax_uniform(e);
            contrib = (double)((table_f(u * diff) + EPSV) * diff * (1.0f / (float)NMC));
        }
#pragma unroll
        for (int o = 16; o; o >>= 1) contrib += __shfl_down_sync(0xffffffffu, contrib, o);
        if ((tid & 31) == 0) wsum[tid >> 5] = contrib;
        __syncthreads();
        if (tid == 0) {
            double tot = 0.0;
#pragma unroll
            for (int w = 0; w < 8; w++) tot += wsum[w];
            atomicAdd(&g_lamb_ints, tot);
        }
    }
    // completion: last block finalizes (deterministic; g_done reset each call)
    if (tid == 0) {
        __threadfence();
        unsigned v = atomicAdd(&g_done, 1u);
        if (v == (unsigned)(TOTAL_BLOCKS - 1)) {
            double sl = atomicAdd(&g_sum_log, 0.0);
            double li = atomicAdd(&g_lamb_ints, 0.0);
            double ints = li + (double)NBATCH * 100.0 * (double)__ldg(bg);
            out[0] = (float)(-(sl - ints) / (double)NBATCH);
        }
    }
}

// ---------------- launch ----------------
extern "C" void kernel_launch(void* const* d_in, const int* in_sizes, int n_in,
                              void* d_out, int out_size) {
    const float* seq_pads  = (const float*)d_in[0];   // [16,384,1]
    const int*   seq_lens  = (const int*)  d_in[1];   // [16]
    const float* background= (const float*)d_in[2];   // [1]
    const float* W1 = (const float*)d_in[3];
    const float* b1 = (const float*)d_in[4];
    const float* W2 = (const float*)d_in[5];
    const float* b2 = (const float*)d_in[6];
    const float* W3 = (const float*)d_in[7];
    const float* b3 = (const float*)d_in[8];
    const float* W4 = (const float*)d_in[9];
    const float* b4 = (const float*)d_in[10];
    float* out = (float*)d_out;

    build_coef_kernel<<<NTAB / 16, 256>>>(W1, b1, W2, b2, W3, b3, W4, b4);
    fused_kernel<<<TOTAL_BLOCKS, 256>>>(seq_pads, seq_lens, background, out);
}

// round 9
// speedup vs baseline: 2.3896x; 1.1333x over previous
#include <cuda_runtime.h>
#include <math.h>
#include <stdint.h>

#define T_ENDF   100.0f
#define NTAB     2048
#define NBATCH   16
#define MAXLEN   384
#define NMC      15
#define EPSV     1e-10f
#define U_HALF   46080u

#define BUILD_BLOCKS 128                 /* NTAB/16 intervals per block */
#define PAIR_BLOCKS  768                 /* 16*384 warps / 8 warps per block */
#define MC_BLOCKS    360                 /* 92160 / 256 */
#define PAIR_BASE    BUILD_BLOCKS
#define MC_BASE      (BUILD_BLOCKS + PAIR_BLOCKS)
#define TOTAL_BLOCKS (BUILD_BLOCKS + PAIR_BLOCKS + MC_BLOCKS)

// ---------------- device scratch (no allocations allowed) ----------------
__device__ float4  g_coef[NTAB];
__device__ float   g_part_log[PAIR_BLOCKS];
__device__ float   g_part_int[MC_BLOCKS];
__device__ unsigned g_tab_done;          // static-init 0; finalizer resets to 0
__device__ unsigned g_done;              // static-init 0; finalizer resets to 0

// ---------------- small helpers ----------------
__device__ __forceinline__ float softplusf(float x) {
    return fmaxf(x, 0.f) + log1pf(expf(-fabsf(x)));
}

__device__ __forceinline__ uint32_t rotl32(uint32_t x, int r) {
    return (x << r) | (x >> (32 - r));
}

// Reproduce jax.random.uniform(jax.random.key(42), (15,16,384)) element idx.
__device__ __forceinline__ float jax_uniform(uint32_t idx) {
    const uint32_t k0 = 0u, k1 = 42u;
    const uint32_t k2 = 0x1BD11BDAu ^ k0 ^ k1;
    bool lo = idx < U_HALF;
    uint32_t x0 = lo ? idx : idx - U_HALF;
    uint32_t x1 = lo ? idx + U_HALF : idx;
    x0 += k0; x1 += k1;
#define TF_RND(r) { x0 += x1; x1 = rotl32(x1, r); x1 ^= x0; }
    TF_RND(13) TF_RND(15) TF_RND(26) TF_RND(6);  x0 += k1; x1 += k2 + 1u;
    TF_RND(17) TF_RND(29) TF_RND(16) TF_RND(24); x0 += k2; x1 += k0 + 2u;
    TF_RND(13) TF_RND(15) TF_RND(26) TF_RND(6);  x0 += k0; x1 += k1 + 3u;
    TF_RND(17) TF_RND(29) TF_RND(16) TF_RND(24); x0 += k1; x1 += k2 + 4u;
    TF_RND(13) TF_RND(15) TF_RND(26) TF_RND(6);  x0 += k2; x1 += k0 + 5u;
#undef TF_RND
    uint32_t bits = lo ? x0 : x1;
    return __uint_as_float(0x3f800000u | (bits >> 9)) - 1.0f;
}

// Cubic lookup of f(x), x in [0, 100]: one LDG.128 + 3 FMA.
__device__ __forceinline__ float table_f(float x) {
    const float scale = (float)(NTAB - 1) / T_ENDF;
    float p = x * scale;
    int k = __float2int_rd(p);
    k = max(0, min(k, NTAB - 2));
    float fr = p - (float)k;
    float4 c = g_coef[k];
    return fmaf(fmaf(fmaf(c.w, fr, c.z), fr, c.y), fr, c.x);
}

// ---------------- build helpers ----------------
#define BROWS 20
#define ASTRIDE 132   /* multiple of 4 for LDS.128; broadcast reads: no conflicts */

__device__ __forceinline__ void layer20(const float* __restrict__ Ash,
                                        float* __restrict__ Csh,
                                        const float* __restrict__ W,
                                        const float* __restrict__ bias,
                                        int tid) {
    int grp = tid >> 7;          // 0: rows 0-9, 1: rows 10-19
    int c = tid & 127;
    int r0 = grp * 10;
    float acc[10];
    float bv = __ldg(bias + c);
#pragma unroll
    for (int q = 0; q < 10; q++) acc[q] = bv;
    for (int k4 = 0; k4 < 32; k4++) {
        float w0 = __ldg(W + (k4 * 4 + 0) * 128 + c);
        float w1 = __ldg(W + (k4 * 4 + 1) * 128 + c);
        float w2 = __ldg(W + (k4 * 4 + 2) * 128 + c);
        float w3 = __ldg(W + (k4 * 4 + 3) * 128 + c);
#pragma unroll
        for (int q = 0; q < 10; q++) {
            float4 a = *(const float4*)(Ash + (r0 + q) * ASTRIDE + k4 * 4);
            acc[q] = fmaf(a.x, w0, acc[q]);
            acc[q] = fmaf(a.y, w1, acc[q]);
            acc[q] = fmaf(a.z, w2, acc[q]);
            acc[q] = fmaf(a.w, w3, acc[q]);
        }
    }
#pragma unroll
    for (int q = 0; q < 10; q++)
        Csh[(r0 + q) * ASTRIDE + c] = tanhf(acc[q]);
}

// ---------------- the single kernel ----------------
// bids [0,128): build 16 table intervals each (one block per SM, wave-1
//               resident since 128 <= 148), release g_tab_done.
// bids [128,896): pairs — one warp per (b,i), 8 warps/block.
// bids [896,1256): MC — one thread per (s,b,l).
// Last block to finish reduces per-block partials, writes out, resets counters.
__global__ __launch_bounds__(256) void mega_kernel(
    const float* __restrict__ t, const int* __restrict__ lens,
    const float* __restrict__ bg, float* __restrict__ out,
    const float* __restrict__ W1, const float* __restrict__ b1,
    const float* __restrict__ W2, const float* __restrict__ b2,
    const float* __restrict__ W3, const float* __restrict__ b3,
    const float* __restrict__ W4, const float* __restrict__ b4) {
    __shared__ float A[BROWS * ASTRIDE];
    __shared__ float C[BROWS * ASTRIDE];
    __shared__ float val[BROWS];
    __shared__ float wsum[8];
    __shared__ float red[256];
    __shared__ bool  isLast;
    const int tid = threadIdx.x;
    const int bid = blockIdx.x;

    if (bid < BUILD_BLOCKS) {
        // ---------------- builder ----------------
        const float h = T_ENDF / (float)(NTAB - 1);
        const int base = bid * 16 - 1;          // grid-point index of local row 0
        for (int e = tid; e < BROWS * 128; e += 256) {
            int j = e >> 7, c = e & 127;
            int p = base + j;
            p = max(0, min(p, NTAB - 1));
            float x = (float)p * h;
            A[j * ASTRIDE + c] = tanhf(fmaf(x, __ldg(W1 + c), __ldg(b1 + c)));
        }
        __syncthreads();
        layer20(A, C, W2, b2, tid);   // layer 2
        __syncthreads();
        layer20(C, A, W3, b3, tid);   // layer 3
        __syncthreads();
        if (tid < BROWS * 8) {        // head: 8 threads per row
            int j = tid >> 3, l8 = tid & 7;
            float acc = 0.f;
#pragma unroll
            for (int q = 0; q < 16; q++) {
                int cc = l8 + (q << 3);
                acc = fmaf(A[j * ASTRIDE + cc], __ldg(W4 + cc), acc);
            }
            acc += __shfl_down_sync(0xffffffffu, acc, 4, 8);
            acc += __shfl_down_sync(0xffffffffu, acc, 2, 8);
            acc += __shfl_down_sync(0xffffffffu, acc, 1, 8);
            if (l8 == 0) val[j] = softplusf(acc + __ldg(b4));
        }
        __syncthreads();
        if (tid < 16) {               // Catmull-Rom coefficients
            int k = bid * 16 + tid;
            if (k <= NTAB - 2) {
                float p0 = val[tid], p1 = val[tid + 1], p2 = val[tid + 2], p3 = val[tid + 3];
                float m1 = (k == 0)
                    ? fmaf(-1.5f, p1, fmaf(2.0f, p2, -0.5f * p3))
                    : 0.5f * (p2 - p0);
                float m2 = (k == NTAB - 2)
                    ? fmaf(1.5f, p2, fmaf(-2.0f, p1, 0.5f * p0))
                    : 0.5f * (p3 - p1);
                float d = p2 - p1;
                g_coef[k] = make_float4(p1, m1, 3.f * d - 2.f * m1 - m2, m1 + m2 - 2.f * d);
            }
        }
        __syncthreads();
        if (tid == 0) {               // release table (threadFenceReduction pattern)
            __threadfence();
            atomicAdd(&g_tab_done, 1u);
        }
    } else {
        // ---------------- consumer: wait for the table ----------------
        if (tid == 0) {
            volatile unsigned* p = &g_tab_done;
            while (*p < (unsigned)BUILD_BLOCKS) __nanosleep(512);
        }
        __syncthreads();
        __threadfence();              // acquire before reading g_coef

        if (bid < MC_BASE) {
            // ---------------- pairs: one warp per (b, i) ----------------
            int wid_in_blk = tid >> 5;
            int lane = tid & 31;
            int wg = (bid - PAIR_BASE) * 8 + wid_in_blk;
            int b = wg / MAXLEN;
            int i = wg % MAXLEN;
            float background = __ldg(bg);
            float contrib = 0.0f;
            int len = __ldg(lens + b);
            if (i == 0) {
                if (lane == 0) contrib = logf(background);
            } else if (i < len) {
                const float* tb = t + b * MAXLEN;
                float ti = __ldg(tb + i);
                float s = 0.f;
                for (int j = lane; j < i; j += 32)
                    s += table_f(ti - __ldg(tb + j));
#pragma unroll
                for (int o = 16; o; o >>= 1) s += __shfl_down_sync(0xffffffffu, s, o);
                if (lane == 0) contrib = logf(s + background);
            }
            if (lane == 0) wsum[wid_in_blk] = contrib;
            __syncthreads();
            if (tid == 0) {
                float tot = 0.f;
#pragma unroll
                for (int w = 0; w < 8; w++) tot += wsum[w];
                g_part_log[bid - PAIR_BASE] = tot;
            }
        } else {
            // ---------------- MC: one thread per (s, b, l) ----------------
            uint32_t e = (bid - MC_BASE) * 256u + (uint32_t)tid;  // s*6144 + b*384 + l
            uint32_t r = e % (NBATCH * MAXLEN);
            int b = r / MAXLEN;
            int l = r % MAXLEN;
            float contrib = 0.0f;
            if (l < __ldg(lens + b)) {
                float diff = T_ENDF - __ldg(t + r);
                float u = jax_uniform(e);
                contrib = (table_f(u * diff) + EPSV) * diff * (1.0f / (float)NMC);
            }
#pragma unroll
            for (int o = 16; o; o >>= 1) contrib += __shfl_down_sync(0xffffffffu, contrib, o);
            if ((tid & 31) == 0) wsum[tid >> 5] = contrib;
            __syncthreads();
            if (tid == 0) {
                float tot = 0.f;
#pragma unroll
                for (int w = 0; w < 8; w++) tot += wsum[w];
                g_part_int[bid - MC_BASE] = tot;
            }
        }
    }

    // ---------------- completion + finalize (all blocks converge here) ----
    if (tid == 0) {
        __threadfence();
        unsigned v = atomicAdd(&g_done, 1u);
        isLast = (v == (unsigned)(TOTAL_BLOCKS - 1));
    }
    __syncthreads();
    if (isLast) {
        // fp32 tree reduction of partials (magnitudes ~O(10), error ~1e-6 rel)
        float sl = 0.f;
        for (int i2 = tid; i2 < PAIR_BLOCKS; i2 += 256) sl += g_part_log[i2];
        float si = 0.f;
        for (int i2 = tid; i2 < MC_BLOCKS; i2 += 256) si += g_part_int[i2];
        red[tid] = sl;
        __syncthreads();
#pragma unroll
        for (int s2 = 128; s2; s2 >>= 1) {
            if (tid < s2) red[tid] += red[tid + s2];
            __syncthreads();
        }
        float sum_log = red[0];
        __syncthreads();
        red[tid] = si;
        __syncthreads();
#pragma unroll
        for (int s2 = 128; s2; s2 >>= 1) {
            if (tid < s2) red[tid] += red[tid + s2];
            __syncthreads();
        }
        if (tid == 0) {
            double ints = (double)red[0] + (double)NBATCH * 100.0 * (double)__ldg(bg);
            out[0] = (float)(-((double)sum_log - ints) / (double)NBATCH);
            g_done = 0u;          // leave-clean for next graph replay
            g_tab_done = 0u;
        }
    }
}

// ---------------- launch ----------------
extern "C" void kernel_launch(void* const* d_in, const int* in_sizes, int n_in,
                              void* d_out, int out_size) {
    const float* seq_pads  = (const float*)d_in[0];   // [16,384,1]
    const int*   seq_lens  = (const int*)  d_in[1];   // [16]
    const float* background= (const float*)d_in[2];   // [1]
    const float* W1 = (const float*)d_in[3];
    const float* b1 = (const float*)d_in[4];
    const float* W2 = (const float*)d_in[5];
    const float* b2 = (const float*)d_in[6];
    const float* W3 = (const float*)d_in[7];
    const float* b3 = (const float*)d_in[8];
    const float* W4 = (const float*)d_in[9];
    const float* b4 = (const float*)d_in[10];
    float* out = (float*)d_out;

    mega_kernel<<<TOTAL_BLOCKS, 256>>>(seq_pads, seq_lens, background, out,
                                       W1, b1, W2, b2, W3, b3, W4, b4);
}